// round 2
// baseline (speedup 1.0000x reference)
#include <cuda_runtime.h>
#include <math.h>

#define BB 2
#define TT 2048
#define CC 2048
#define HH 16
#define DD 128
#define C3 (3*CC)
#define BT (BB*TT)

// ---------------- device scratch (static: no allocations allowed) ----------------
__device__ float g_qkv[(size_t)BT * C3];   // [B,T,3C] fp32 (~100MB)
__device__ float g_attn[(size_t)BT * CC];  // [B,T,C] attention output (~33MB)
__device__ float g_cos[TT * 64];
__device__ float g_sin[TT * 64];
__device__ int   g_len[BB];

// ---------------- lengths from padding mask (dtype auto-detect) ----------------
__global__ void lengths_kernel(const void* mask) {
    __shared__ int ssum[256];
    int b = blockIdx.x;
    unsigned int w0 = *(const unsigned int*)mask;   // first 4 bytes; mask starts with trues
    int cnt = 0;
    if (w0 == 0x01010101u) {                         // bool / uint8 layout
        const unsigned char* m = (const unsigned char*)mask + (size_t)b * TT;
        for (int i = threadIdx.x; i < TT; i += 256) cnt += (m[i] != 0);
    } else if (w0 == 0x3F800000u) {                  // float32 layout
        const float* m = (const float*)mask + (size_t)b * TT;
        for (int i = threadIdx.x; i < TT; i += 256) cnt += (m[i] != 0.0f);
    } else {                                         // int32 layout
        const int* m = (const int*)mask + (size_t)b * TT;
        for (int i = threadIdx.x; i < TT; i += 256) cnt += (m[i] != 0);
    }
    ssum[threadIdx.x] = cnt;
    __syncthreads();
    for (int s = 128; s > 0; s >>= 1) {
        if (threadIdx.x < s) ssum[threadIdx.x] += ssum[threadIdx.x + s];
        __syncthreads();
    }
    if (threadIdx.x == 0) g_len[b] = ssum[0];
}

// ---------------- RoPE tables (match fp32 reference semantics) ----------------
__global__ void rope_table_kernel() {
    int idx = blockIdx.x * blockDim.x + threadIdx.x;
    if (idx >= TT * 64) return;
    int t = idx >> 6, i = idx & 63;
    // inv_freq computed like f32 reference; angle rounded to f32, then accurate sincos
    float invf = (float)(1.0 / pow(10000.0, (double)i / 64.0));
    float ang = (float)t * invf;                     // fp32 multiply, as in reference
    double a = (double)ang;
    g_cos[idx] = (float)cos(a);
    g_sin[idx] = (float)sin(a);
}

// ---------------- in-place RoPE on Q and K slices of g_qkv ----------------
__global__ void rope_apply_kernel() {
    int idx = blockIdx.x * blockDim.x + threadIdx.x;  // BB*TT*2*HH*64 threads
    int i = idx & 63; int r = idx >> 6;
    int h = r & (HH - 1); r >>= 4;
    int w = r & 1; r >>= 1;                           // 0 = Q, 1 = K
    int t = r & (TT - 1); r >>= 11;
    int b = r;
    size_t base = ((size_t)(b * TT + t)) * C3 + (size_t)w * CC + (size_t)h * DD;
    float c = g_cos[t * 64 + i], s = g_sin[t * 64 + i];
    float x1 = g_qkv[base + i], x2 = g_qkv[base + 64 + i];
    g_qkv[base + i]      = x1 * c - x2 * s;
    g_qkv[base + 64 + i] = x2 * c + x1 * s;
}

// ---------------- fp32 SGEMM: C[M,N] = A[M,K] @ B[K,N], all dims %128==0, K%8==0 ----------------
__global__ __launch_bounds__(256) void sgemm_kernel(
    const float* __restrict__ A, const float* __restrict__ Bm, float* __restrict__ Cm,
    int M, int N, int K)
{
    __shared__ float As[8][132];   // transposed A tile, padded stride -> conflict-free
    __shared__ float Bs[8][128];
    const int tid = threadIdx.x;
    const int tx = tid & 15, ty = tid >> 4;
    const int row0 = blockIdx.y * 128;
    const int col0 = blockIdx.x * 128;

    float acc[8][8];
#pragma unroll
    for (int i = 0; i < 8; i++)
#pragma unroll
        for (int j = 0; j < 8; j++) acc[i][j] = 0.f;

    for (int k0 = 0; k0 < K; k0 += 8) {
#pragma unroll
        for (int l = 0; l < 4; l++) {
            int lin = l * 256 + tid;
            int m = lin >> 3, kk = lin & 7;
            As[kk][m] = A[(size_t)(row0 + m) * K + k0 + kk];
        }
        {
            int kk = tid >> 5, n4 = (tid & 31) << 2;
            *(float4*)&Bs[kk][n4] = *(const float4*)&Bm[(size_t)(k0 + kk) * N + col0 + n4];
        }
        __syncthreads();
#pragma unroll
        for (int kk = 0; kk < 8; kk++) {
            float4 a0 = *(float4*)&As[kk][ty * 8];
            float4 a1 = *(float4*)&As[kk][ty * 8 + 4];
            float4 b0 = *(float4*)&Bs[kk][tx * 4];         // cols tx*4..+3
            float4 b1 = *(float4*)&Bs[kk][64 + tx * 4];    // cols 64+tx*4..+3  (conflict-free)
            float av[8] = {a0.x, a0.y, a0.z, a0.w, a1.x, a1.y, a1.z, a1.w};
            float bv[8] = {b0.x, b0.y, b0.z, b0.w, b1.x, b1.y, b1.z, b1.w};
#pragma unroll
            for (int i = 0; i < 8; i++)
#pragma unroll
                for (int j = 0; j < 8; j++) acc[i][j] += av[i] * bv[j];
        }
        __syncthreads();
    }
#pragma unroll
    for (int i = 0; i < 8; i++) {
        float* crow = Cm + (size_t)(row0 + ty * 8 + i) * N + col0;
        *(float4*)&crow[tx * 4]      = make_float4(acc[i][0], acc[i][1], acc[i][2], acc[i][3]);
        *(float4*)&crow[64 + tx * 4] = make_float4(acc[i][4], acc[i][5], acc[i][6], acc[i][7]);
    }
}

// ---------------- fp32 flash attention, causal, 64x64 tiles, D=128 ----------------
#define ATT_SMEM_FLOATS (3 * 64 * 132 + 64 * 68 + 3 * 64)
#define ATT_SMEM_BYTES  (ATT_SMEM_FLOATS * 4)

__global__ __launch_bounds__(256) void attn_kernel() {
    extern __shared__ float sm[];
    float* Qs = sm;                       // [64][132]
    float* Ks = sm + 64 * 132;            // [64][132]
    float* Vs = sm + 2 * 64 * 132;        // [64][132]
    float* Ss = sm + 3 * 64 * 132;        // [64][68]
    float* mrow = Ss + 64 * 68;
    float* lrow = mrow + 64;
    float* crow = lrow + 64;

    const int tid = threadIdx.x;
    const int tx = tid & 15, ty = tid >> 4;
    const int bh = blockIdx.y;
    const int b = bh >> 4, h = bh & 15;
    const int qi = (int)gridDim.x - 1 - (int)blockIdx.x;  // heavy tiles launch first
    const int qbase = qi * 64;

    const float* Qg = g_qkv + (size_t)b * TT * C3 + (size_t)h * DD;
    const float* Kg = Qg + CC;
    const float* Vg = Qg + 2 * CC;

    // load Q tile (64 x 128)
#pragma unroll
    for (int l = 0; l < 8; l++) {
        int lin = l * 256 + tid;
        int row = lin >> 5, c4 = (lin & 31) << 2;
        *(float4*)&Qs[row * 132 + c4] =
            *(const float4*)&Qg[(size_t)(qbase + row) * C3 + c4];
    }
    if (tid < 64) { mrow[tid] = -INFINITY; lrow[tid] = 0.f; }
    float o[4][8];
#pragma unroll
    for (int i = 0; i < 4; i++)
#pragma unroll
        for (int j = 0; j < 8; j++) o[i][j] = 0.f;
    __syncthreads();

    const float scale = 0.08838834764831845f;  // 1/sqrt(128)

    for (int kt = 0; kt <= qi; kt++) {
        // load K,V tiles
#pragma unroll
        for (int l = 0; l < 8; l++) {
            int lin = l * 256 + tid;
            int row = lin >> 5, c4 = (lin & 31) << 2;
            size_t gofs = (size_t)(kt * 64 + row) * C3 + c4;
            *(float4*)&Ks[row * 132 + c4] = *(const float4*)&Kg[gofs];
            *(float4*)&Vs[row * 132 + c4] = *(const float4*)&Vg[gofs];
        }
        __syncthreads();

        // scores: 4 q-rows (ty*4+i) x 4 k-cols (tx+16j)
        float sc[4][4];
#pragma unroll
        for (int i = 0; i < 4; i++)
#pragma unroll
            for (int j = 0; j < 4; j++) sc[i][j] = 0.f;

        for (int d = 0; d < 128; d += 4) {
            float4 q0 = *(float4*)&Qs[(ty * 4 + 0) * 132 + d];
            float4 q1 = *(float4*)&Qs[(ty * 4 + 1) * 132 + d];
            float4 q2 = *(float4*)&Qs[(ty * 4 + 2) * 132 + d];
            float4 q3 = *(float4*)&Qs[(ty * 4 + 3) * 132 + d];
            float4 k0 = *(float4*)&Ks[(tx +  0) * 132 + d];
            float4 k1 = *(float4*)&Ks[(tx + 16) * 132 + d];
            float4 k2 = *(float4*)&Ks[(tx + 32) * 132 + d];
            float4 k3 = *(float4*)&Ks[(tx + 48) * 132 + d];
            float4 qv[4] = {q0, q1, q2, q3};
            float4 kv[4] = {k0, k1, k2, k3};
#pragma unroll
            for (int i = 0; i < 4; i++)
#pragma unroll
                for (int j = 0; j < 4; j++) {
                    sc[i][j] += qv[i].x * kv[j].x + qv[i].y * kv[j].y
                              + qv[i].z * kv[j].z + qv[i].w * kv[j].w;
                }
        }

        // write scaled + masked scores to shared
#pragma unroll
        for (int i = 0; i < 4; i++) {
            int qr = ty * 4 + i;
#pragma unroll
            for (int j = 0; j < 4; j++) {
                int kc = tx + 16 * j;
                float v = sc[i][j] * scale;
                if (kt == qi && kc > qr) v = -INFINITY;   // causal (diag tile)
                Ss[qr * 68 + kc] = v;
            }
        }
        __syncthreads();

        // online softmax: 4 lanes per row
        {
            int r = tid >> 2, sub = tid & 3;
            int cbase = sub * 16;
            float mx = -INFINITY;
#pragma unroll
            for (int c = 0; c < 16; c++) mx = fmaxf(mx, Ss[r * 68 + cbase + c]);
            mx = fmaxf(mx, __shfl_xor_sync(0xffffffffu, mx, 1));
            mx = fmaxf(mx, __shfl_xor_sync(0xffffffffu, mx, 2));
            float mold = mrow[r];
            float mnew = fmaxf(mold, mx);
            float s = 0.f;
#pragma unroll
            for (int c = 0; c < 16; c++) {
                float p = expf(Ss[r * 68 + cbase + c] - mnew);
                Ss[r * 68 + cbase + c] = p;
                s += p;
            }
            s += __shfl_xor_sync(0xffffffffu, s, 1);
            s += __shfl_xor_sync(0xffffffffu, s, 2);
            if (sub == 0) {
                float cf = expf(mold - mnew);   // mold=-inf -> 0; mnew always finite
                lrow[r] = lrow[r] * cf + s;
                mrow[r] = mnew;
                crow[r] = cf;
            }
        }
        __syncthreads();

        // rescale O, then O += P @ V  (4 rows x 8 cols: tx*4..+3 and 64+tx*4..+3)
        float cf[4];
#pragma unroll
        for (int i = 0; i < 4; i++) cf[i] = crow[ty * 4 + i];
#pragma unroll
        for (int i = 0; i < 4; i++)
#pragma unroll
            for (int j = 0; j < 8; j++) o[i][j] *= cf[i];

        for (int kk = 0; kk < 64; kk++) {
            float p0 = Ss[(ty * 4 + 0) * 68 + kk];
            float p1 = Ss[(ty * 4 + 1) * 68 + kk];
            float p2 = Ss[(ty * 4 + 2) * 68 + kk];
            float p3 = Ss[(ty * 4 + 3) * 68 + kk];
            float4 v0 = *(float4*)&Vs[kk * 132 + tx * 4];
            float4 v1 = *(float4*)&Vs[kk * 132 + 64 + tx * 4];
            float pv[4] = {p0, p1, p2, p3};
#pragma unroll
            for (int i = 0; i < 4; i++) {
                o[i][0] += pv[i] * v0.x; o[i][1] += pv[i] * v0.y;
                o[i][2] += pv[i] * v0.z; o[i][3] += pv[i] * v0.w;
                o[i][4] += pv[i] * v1.x; o[i][5] += pv[i] * v1.y;
                o[i][6] += pv[i] * v1.z; o[i][7] += pv[i] * v1.w;
            }
        }
        __syncthreads();
    }

    // epilogue: normalize, zero padded rows, write [B,T,C]
    int len = g_len[b];
#pragma unroll
    for (int i = 0; i < 4; i++) {
        int r = ty * 4 + i;
        int t = qbase + r;
        float inv = 1.0f / lrow[r];
        float* dst = g_attn + ((size_t)b * TT + t) * CC + (size_t)h * DD;
        float4 a0, a1;
        if (t >= len) {
            a0 = make_float4(0.f, 0.f, 0.f, 0.f);
            a1 = a0;
        } else {
            a0 = make_float4(o[i][0] * inv, o[i][1] * inv, o[i][2] * inv, o[i][3] * inv);
            a1 = make_float4(o[i][4] * inv, o[i][5] * inv, o[i][6] * inv, o[i][7] * inv);
        }
        *(float4*)&dst[tx * 4]      = a0;
        *(float4*)&dst[64 + tx * 4] = a1;
    }
}

// ---------------- launch ----------------
extern "C" void kernel_launch(void* const* d_in, const int* in_sizes, int n_in,
                              void* d_out, int out_size) {
    const float* x    = (const float*)d_in[0];
    const void*  mask = d_in[1];
    const float* Wqkv = (const float*)d_in[2];
    const float* Wout = (const float*)d_in[3];
    float* out = (float*)d_out;

    float* qkv;  cudaGetSymbolAddress((void**)&qkv,  g_qkv);
    float* attn; cudaGetSymbolAddress((void**)&attn, g_attn);

    lengths_kernel<<<BB, 256>>>(mask);
    rope_table_kernel<<<(TT * 64 + 255) / 256, 256>>>();

    // qkv = x @ Wqkv  : [4096,2048] @ [2048,6144]
    sgemm_kernel<<<dim3(C3 / 128, BT / 128), 256>>>(x, Wqkv, qkv, BT, C3, CC);

    // RoPE in place on Q,K
    rope_apply_kernel<<<(BB * TT * 2 * HH * 64) / 256, 256>>>();

    // causal flash attention
    cudaFuncSetAttribute(attn_kernel, cudaFuncAttributeMaxDynamicSharedMemorySize, ATT_SMEM_BYTES);
    attn_kernel<<<dim3(TT / 64, BB * HH), 256, ATT_SMEM_BYTES>>>();

    // out = attn @ Wout : [4096,2048] @ [2048,2048]
    sgemm_kernel<<<dim3(CC / 128, BT / 128), 256>>>(attn, Wout, out, BT, CC, CC);
}

// round 4
// speedup vs baseline: 1.2887x; 1.2887x over previous
#include <cuda_runtime.h>
#include <math.h>

#define BB 2
#define TT 2048
#define CC 2048
#define HH 16
#define DD 128
#define C3 (3*CC)
#define BT (BB*TT)

// ---------------- device scratch (static: no allocations allowed) ----------------
__device__ float g_qkv[(size_t)BT * C3];   // [B,T,3C] fp32 (~100MB)
__device__ float g_attn[(size_t)BT * CC];  // [B,T,C] attention output (~33MB)
__device__ float g_cos[TT * 64];
__device__ float g_sin[TT * 64];
__device__ int   g_len[BB];

// ---------------- lengths from padding mask (dtype auto-detect) ----------------
__global__ void lengths_kernel(const void* mask) {
    __shared__ int ssum[256];
    int b = blockIdx.x;
    unsigned int w0 = *(const unsigned int*)mask;   // first 4 bytes; mask starts with trues
    int cnt = 0;
    if (w0 == 0x01010101u) {                         // bool / uint8 layout
        const unsigned char* m = (const unsigned char*)mask + (size_t)b * TT;
        for (int i = threadIdx.x; i < TT; i += 256) cnt += (m[i] != 0);
    } else if (w0 == 0x3F800000u) {                  // float32 layout
        const float* m = (const float*)mask + (size_t)b * TT;
        for (int i = threadIdx.x; i < TT; i += 256) cnt += (m[i] != 0.0f);
    } else {                                         // int32 layout
        const int* m = (const int*)mask + (size_t)b * TT;
        for (int i = threadIdx.x; i < TT; i += 256) cnt += (m[i] != 0);
    }
    ssum[threadIdx.x] = cnt;
    __syncthreads();
    for (int s = 128; s > 0; s >>= 1) {
        if (threadIdx.x < s) ssum[threadIdx.x] += ssum[threadIdx.x + s];
        __syncthreads();
    }
    if (threadIdx.x == 0) g_len[b] = ssum[0];
}

// ---------------- RoPE tables (match fp32 reference semantics) ----------------
__global__ void rope_table_kernel() {
    int idx = blockIdx.x * blockDim.x + threadIdx.x;
    if (idx >= TT * 64) return;
    int t = idx >> 6, i = idx & 63;
    float invf = (float)(1.0 / pow(10000.0, (double)i / 64.0));
    float ang = (float)t * invf;                     // fp32 multiply, as in reference
    double a = (double)ang;
    g_cos[idx] = (float)cos(a);
    g_sin[idx] = (float)sin(a);
}

// ---------------- in-place RoPE on Q and K slices of g_qkv ----------------
__global__ void rope_apply_kernel() {
    int idx = blockIdx.x * blockDim.x + threadIdx.x;  // BB*TT*2*HH*64 threads
    int i = idx & 63; int r = idx >> 6;
    int h = r & (HH - 1); r >>= 4;
    int w = r & 1; r >>= 1;                           // 0 = Q, 1 = K
    int t = r & (TT - 1); r >>= 11;
    int b = r;
    size_t base = ((size_t)(b * TT + t)) * C3 + (size_t)w * CC + (size_t)h * DD;
    float c = g_cos[t * 64 + i], s = g_sin[t * 64 + i];
    float x1 = g_qkv[base + i], x2 = g_qkv[base + 64 + i];
    g_qkv[base + i]      = x1 * c - x2 * s;
    g_qkv[base + 64 + i] = x2 * c + x1 * s;
}

// ================= 3xTF32 tensor-core GEMM: C[M,N] = A[M,K] @ B[K,N] ==============
// CTA tile 128x128, 4 warps (2x2) of 64x64 warp tiles, KC=32 double-buffered cp.async.
// Each operand split x = hi + lo (tf32 pair); D += Alo*Bhi + Ahi*Blo + Ahi*Bhi.
#define KC 32
#define AS_STRIDE 36            // 32 + 4 pad: a-frag bank = lane  (conflict-free)
#define BS_STRIDE 136           // 128 + 8 pad: b-frag bank = 8*tig+gr (conflict-free)
#define ABUF (128 * AS_STRIDE)
#define BBUF (KC * BS_STRIDE)
#define GEMM_SMEM ((2 * ABUF + 2 * BBUF) * 4)

__device__ __forceinline__ unsigned smem_u32(const void* p) {
    return (unsigned)__cvta_generic_to_shared(p);
}

__device__ __forceinline__ void split_tf32(float x, unsigned &hi, unsigned &lo) {
    unsigned h;
    asm("cvt.rna.tf32.f32 %0, %1;" : "=r"(h) : "f"(x));
    float l = x - __uint_as_float(h);
    unsigned lw;
    asm("cvt.rna.tf32.f32 %0, %1;" : "=r"(lw) : "f"(l));
    hi = h; lo = lw;
}

__device__ __forceinline__ void mma_tf32(float* d, const unsigned* a, const unsigned* b) {
    asm volatile(
        "mma.sync.aligned.m16n8k8.row.col.f32.tf32.tf32.f32 "
        "{%0,%1,%2,%3}, {%4,%5,%6,%7}, {%8,%9}, {%0,%1,%2,%3};"
        : "+f"(d[0]), "+f"(d[1]), "+f"(d[2]), "+f"(d[3])
        : "r"(a[0]), "r"(a[1]), "r"(a[2]), "r"(a[3]), "r"(b[0]), "r"(b[1]));
}

__device__ __forceinline__ void gemm_load_chunk(
    float* As, float* Bs, const float* __restrict__ A, const float* __restrict__ B,
    int row0, int col0, int kc, int K, int N, int tid)
{
#pragma unroll
    for (int i = 0; i < 8; i++) {                     // A tile: 128 x 32
        int idx = i * 128 + tid;
        int row = idx >> 3, seg = (idx & 7) << 2;
        unsigned dst = smem_u32(As + row * AS_STRIDE + seg);
        const float* src = A + (size_t)(row0 + row) * K + kc + seg;
        asm volatile("cp.async.cg.shared.global [%0], [%1], 16;" :: "r"(dst), "l"(src));
    }
#pragma unroll
    for (int i = 0; i < 8; i++) {                     // B tile: 32 x 128
        int idx = i * 128 + tid;
        int row = idx >> 5, seg = (idx & 31) << 2;
        unsigned dst = smem_u32(Bs + row * BS_STRIDE + seg);
        const float* src = B + (size_t)(kc + row) * N + col0 + seg;
        asm volatile("cp.async.cg.shared.global [%0], [%1], 16;" :: "r"(dst), "l"(src));
    }
    asm volatile("cp.async.commit_group;");
}

__global__ __launch_bounds__(128, 2) void gemm_tf32_kernel(
    const float* __restrict__ A, const float* __restrict__ B, float* __restrict__ C,
    int M, int N, int K)
{
    extern __shared__ float sm[];
    float* As = sm;                 // [2][128][AS_STRIDE]
    float* Bs = sm + 2 * ABUF;      // [2][KC][BS_STRIDE]
    const int tid  = threadIdx.x;
    const int lane = tid & 31, warp = tid >> 5;
    const int wr = warp >> 1, wc = warp & 1;
    const int gr = lane >> 2, tig = lane & 3;
    const int row0 = blockIdx.y * 128, col0 = blockIdx.x * 128;

    float acc[4][8][4];
#pragma unroll
    for (int mi = 0; mi < 4; mi++)
#pragma unroll
        for (int ni = 0; ni < 8; ni++)
#pragma unroll
            for (int r = 0; r < 4; r++) acc[mi][ni][r] = 0.f;

    const int nc = K / KC;
    gemm_load_chunk(As, Bs, A, B, row0, col0, 0, K, N, tid);

    for (int c = 0; c < nc; c++) {
        if (c + 1 < nc) {
            gemm_load_chunk(As + ((c + 1) & 1) * ABUF, Bs + ((c + 1) & 1) * BBUF,
                            A, B, row0, col0, (c + 1) * KC, K, N, tid);
            asm volatile("cp.async.wait_group 1;");
        } else {
            asm volatile("cp.async.wait_group 0;");
        }
        __syncthreads();

        const float* a = As + (c & 1) * ABUF;
        const float* b = Bs + (c & 1) * BBUF;
#pragma unroll
        for (int ks = 0; ks < 4; ks++) {
            const int k0 = ks * 8;
            unsigned afh[4][4], afl[4][4], bfh[8][2], bfl[8][2];
#pragma unroll
            for (int mi = 0; mi < 4; mi++) {
                int m0 = wr * 64 + mi * 16;
                split_tf32(a[(m0 + gr)     * AS_STRIDE + k0 + tig],     afh[mi][0], afl[mi][0]);
                split_tf32(a[(m0 + 8 + gr) * AS_STRIDE + k0 + tig],     afh[mi][1], afl[mi][1]);
                split_tf32(a[(m0 + gr)     * AS_STRIDE + k0 + 4 + tig], afh[mi][2], afl[mi][2]);
                split_tf32(a[(m0 + 8 + gr) * AS_STRIDE + k0 + 4 + tig], afh[mi][3], afl[mi][3]);
            }
#pragma unroll
            for (int ni = 0; ni < 8; ni++) {
                int n0 = wc * 64 + ni * 8;
                split_tf32(b[(k0 + tig)     * BS_STRIDE + n0 + gr], bfh[ni][0], bfl[ni][0]);
                split_tf32(b[(k0 + 4 + tig) * BS_STRIDE + n0 + gr], bfh[ni][1], bfl[ni][1]);
            }
#pragma unroll
            for (int mi = 0; mi < 4; mi++)
#pragma unroll
                for (int ni = 0; ni < 8; ni++) {
                    mma_tf32(acc[mi][ni], afl[mi], bfh[ni]);   // lo*hi
                    mma_tf32(acc[mi][ni], afh[mi], bfl[ni]);   // hi*lo
                    mma_tf32(acc[mi][ni], afh[mi], bfh[ni]);   // hi*hi
                }
        }
        __syncthreads();
    }

    // epilogue: C-frag layout -> global
#pragma unroll
    for (int mi = 0; mi < 4; mi++) {
        int m0 = row0 + wr * 64 + mi * 16;
#pragma unroll
        for (int ni = 0; ni < 8; ni++) {
            int n0 = col0 + wc * 64 + ni * 8 + 2 * tig;
            float* p0 = C + (size_t)(m0 + gr) * N + n0;
            float* p1 = C + (size_t)(m0 + 8 + gr) * N + n0;
            p0[0] = acc[mi][ni][0]; p0[1] = acc[mi][ni][1];
            p1[0] = acc[mi][ni][2]; p1[1] = acc[mi][ni][3];
        }
    }
}

// ---------------- fp32 flash attention, causal, 64x64 tiles, D=128 ----------------
#define ATT_SMEM_FLOATS (3 * 64 * 132 + 64 * 68 + 3 * 64)
#define ATT_SMEM_BYTES  (ATT_SMEM_FLOATS * 4)

__global__ __launch_bounds__(256) void attn_kernel() {
    extern __shared__ float sm[];
    float* Qs = sm;                       // [64][132]
    float* Ks = sm + 64 * 132;            // [64][132]
    float* Vs = sm + 2 * 64 * 132;        // [64][132]
    float* Ss = sm + 3 * 64 * 132;        // [64][68]
    float* mrow = Ss + 64 * 68;
    float* lrow = mrow + 64;
    float* crow = lrow + 64;

    const int tid = threadIdx.x;
    const int tx = tid & 15, ty = tid >> 4;
    const int bh = blockIdx.y;
    const int b = bh >> 4, h = bh & 15;
    const int qi = (int)gridDim.x - 1 - (int)blockIdx.x;  // heavy tiles launch first
    const int qbase = qi * 64;

    const float* Qg = g_qkv + (size_t)b * TT * C3 + (size_t)h * DD;
    const float* Kg = Qg + CC;
    const float* Vg = Qg + 2 * CC;

#pragma unroll
    for (int l = 0; l < 8; l++) {
        int lin = l * 256 + tid;
        int row = lin >> 5, c4 = (lin & 31) << 2;
        *(float4*)&Qs[row * 132 + c4] =
            *(const float4*)&Qg[(size_t)(qbase + row) * C3 + c4];
    }
    if (tid < 64) { mrow[tid] = -INFINITY; lrow[tid] = 0.f; }
    float o[4][8];
#pragma unroll
    for (int i = 0; i < 4; i++)
#pragma unroll
        for (int j = 0; j < 8; j++) o[i][j] = 0.f;
    __syncthreads();

    const float scale = 0.08838834764831845f;  // 1/sqrt(128)

    for (int kt = 0; kt <= qi; kt++) {
#pragma unroll
        for (int l = 0; l < 8; l++) {
            int lin = l * 256 + tid;
            int row = lin >> 5, c4 = (lin & 31) << 2;
            size_t gofs = (size_t)(kt * 64 + row) * C3 + c4;
            *(float4*)&Ks[row * 132 + c4] = *(const float4*)&Kg[gofs];
            *(float4*)&Vs[row * 132 + c4] = *(const float4*)&Vg[gofs];
        }
        __syncthreads();

        float sc[4][4];
#pragma unroll
        for (int i = 0; i < 4; i++)
#pragma unroll
            for (int j = 0; j < 4; j++) sc[i][j] = 0.f;

        for (int d = 0; d < 128; d += 4) {
            float4 q0 = *(float4*)&Qs[(ty * 4 + 0) * 132 + d];
            float4 q1 = *(float4*)&Qs[(ty * 4 + 1) * 132 + d];
            float4 q2 = *(float4*)&Qs[(ty * 4 + 2) * 132 + d];
            float4 q3 = *(float4*)&Qs[(ty * 4 + 3) * 132 + d];
            float4 k0 = *(float4*)&Ks[(tx +  0) * 132 + d];
            float4 k1 = *(float4*)&Ks[(tx + 16) * 132 + d];
            float4 k2 = *(float4*)&Ks[(tx + 32) * 132 + d];
            float4 k3 = *(float4*)&Ks[(tx + 48) * 132 + d];
            float4 qv[4] = {q0, q1, q2, q3};
            float4 kv[4] = {k0, k1, k2, k3};
#pragma unroll
            for (int i = 0; i < 4; i++)
#pragma unroll
                for (int j = 0; j < 4; j++) {
                    sc[i][j] += qv[i].x * kv[j].x + qv[i].y * kv[j].y
                              + qv[i].z * kv[j].z + qv[i].w * kv[j].w;
                }
        }

#pragma unroll
        for (int i = 0; i < 4; i++) {
            int qr = ty * 4 + i;
#pragma unroll
            for (int j = 0; j < 4; j++) {
                int kc = tx + 16 * j;
                float v = sc[i][j] * scale;
                if (kt == qi && kc > qr) v = -INFINITY;   // causal (diag tile)
                Ss[qr * 68 + kc] = v;
            }
        }
        __syncthreads();

        {
            int r = tid >> 2, sub = tid & 3;
            int cbase = sub * 16;
            float mx = -INFINITY;
#pragma unroll
            for (int c = 0; c < 16; c++) mx = fmaxf(mx, Ss[r * 68 + cbase + c]);
            mx = fmaxf(mx, __shfl_xor_sync(0xffffffffu, mx, 1));
            mx = fmaxf(mx, __shfl_xor_sync(0xffffffffu, mx, 2));
            float mold = mrow[r];
            float mnew = fmaxf(mold, mx);
            float s = 0.f;
#pragma unroll
            for (int c = 0; c < 16; c++) {
                float p = expf(Ss[r * 68 + cbase + c] - mnew);
                Ss[r * 68 + cbase + c] = p;
                s += p;
            }
            s += __shfl_xor_sync(0xffffffffu, s, 1);
            s += __shfl_xor_sync(0xffffffffu, s, 2);
            if (sub == 0) {
                float cf = expf(mold - mnew);
                lrow[r] = lrow[r] * cf + s;
                mrow[r] = mnew;
                crow[r] = cf;
            }
        }
        __syncthreads();

        float cf[4];
#pragma unroll
        for (int i = 0; i < 4; i++) cf[i] = crow[ty * 4 + i];
#pragma unroll
        for (int i = 0; i < 4; i++)
#pragma unroll
            for (int j = 0; j < 8; j++) o[i][j] *= cf[i];

        for (int kk = 0; kk < 64; kk++) {
            float p0 = Ss[(ty * 4 + 0) * 68 + kk];
            float p1 = Ss[(ty * 4 + 1) * 68 + kk];
            float p2 = Ss[(ty * 4 + 2) * 68 + kk];
            float p3 = Ss[(ty * 4 + 3) * 68 + kk];
            float4 v0 = *(float4*)&Vs[kk * 132 + tx * 4];
            float4 v1 = *(float4*)&Vs[kk * 132 + 64 + tx * 4];
            float pv[4] = {p0, p1, p2, p3};
#pragma unroll
            for (int i = 0; i < 4; i++) {
                o[i][0] += pv[i] * v0.x; o[i][1] += pv[i] * v0.y;
                o[i][2] += pv[i] * v0.z; o[i][3] += pv[i] * v0.w;
                o[i][4] += pv[i] * v1.x; o[i][5] += pv[i] * v1.y;
                o[i][6] += pv[i] * v1.z; o[i][7] += pv[i] * v1.w;
            }
        }
        __syncthreads();
    }

    int len = g_len[b];
#pragma unroll
    for (int i = 0; i < 4; i++) {
        int r = ty * 4 + i;
        int t = qbase + r;
        float inv = 1.0f / lrow[r];
        float* dst = g_attn + ((size_t)b * TT + t) * CC + (size_t)h * DD;
        float4 a0, a1;
        if (t >= len) {
            a0 = make_float4(0.f, 0.f, 0.f, 0.f);
            a1 = a0;
        } else {
            a0 = make_float4(o[i][0] * inv, o[i][1] * inv, o[i][2] * inv, o[i][3] * inv);
            a1 = make_float4(o[i][4] * inv, o[i][5] * inv, o[i][6] * inv, o[i][7] * inv);
        }
        *(float4*)&dst[tx * 4]      = a0;
        *(float4*)&dst[64 + tx * 4] = a1;
    }
}

// ---------------- launch ----------------
extern "C" void kernel_launch(void* const* d_in, const int* in_sizes, int n_in,
                              void* d_out, int out_size) {
    const float* x    = (const float*)d_in[0];
    const void*  mask = d_in[1];
    const float* Wqkv = (const float*)d_in[2];
    const float* Wout = (const float*)d_in[3];
    float* out = (float*)d_out;

    float* qkv;  cudaGetSymbolAddress((void**)&qkv,  g_qkv);
    float* attn; cudaGetSymbolAddress((void**)&attn, g_attn);

    lengths_kernel<<<BB, 256>>>(mask);
    rope_table_kernel<<<(TT * 64 + 255) / 256, 256>>>();

    cudaFuncSetAttribute(gemm_tf32_kernel, cudaFuncAttributeMaxDynamicSharedMemorySize, GEMM_SMEM);

    // qkv = x @ Wqkv  : [4096,2048] @ [2048,6144]  (3xTF32 tensor cores)
    gemm_tf32_kernel<<<dim3(C3 / 128, BT / 128), 128, GEMM_SMEM>>>(x, Wqkv, qkv, BT, C3, CC);

    // RoPE in place on Q,K
    rope_apply_kernel<<<(BB * TT * 2 * HH * 64) / 256, 256>>>();

    // causal flash attention (fp32 SIMT — tensorize next round)
    cudaFuncSetAttribute(attn_kernel, cudaFuncAttributeMaxDynamicSharedMemorySize, ATT_SMEM_BYTES);
    attn_kernel<<<dim3(TT / 64, BB * HH), 256, ATT_SMEM_BYTES>>>();

    // out = attn @ Wout : [4096,2048] @ [2048,2048]  (3xTF32 tensor cores)
    gemm_tf32_kernel<<<dim3(CC / 128, BT / 128), 128, GEMM_SMEM>>>(attn, Wout, out, BT, CC, CC);
}

// round 5
// speedup vs baseline: 1.6545x; 1.2839x over previous
#include <cuda_runtime.h>
#include <math.h>

#define BB 2
#define TT 2048
#define CC 2048
#define HH 16
#define DD 128
#define C3 (3*CC)
#define BT (BB*TT)

// ---------------- device scratch (static: no allocations allowed) ----------------
__device__ float g_qkv[(size_t)BT * C3];   // [B,T,3C] fp32 (~100MB)
__device__ float g_attn[(size_t)BT * CC];  // [B,T,C] attention output (~33MB)
__device__ float g_cos[TT * 64];
__device__ float g_sin[TT * 64];
__device__ int   g_len[BB];

// ---------------- lengths from padding mask (dtype auto-detect) ----------------
__global__ void lengths_kernel(const void* mask) {
    __shared__ int ssum[256];
    int b = blockIdx.x;
    unsigned int w0 = *(const unsigned int*)mask;
    int cnt = 0;
    if (w0 == 0x01010101u) {
        const unsigned char* m = (const unsigned char*)mask + (size_t)b * TT;
        for (int i = threadIdx.x; i < TT; i += 256) cnt += (m[i] != 0);
    } else if (w0 == 0x3F800000u) {
        const float* m = (const float*)mask + (size_t)b * TT;
        for (int i = threadIdx.x; i < TT; i += 256) cnt += (m[i] != 0.0f);
    } else {
        const int* m = (const int*)mask + (size_t)b * TT;
        for (int i = threadIdx.x; i < TT; i += 256) cnt += (m[i] != 0);
    }
    ssum[threadIdx.x] = cnt;
    __syncthreads();
    for (int s = 128; s > 0; s >>= 1) {
        if (threadIdx.x < s) ssum[threadIdx.x] += ssum[threadIdx.x + s];
        __syncthreads();
    }
    if (threadIdx.x == 0) g_len[b] = ssum[0];
}

// ---------------- RoPE tables (match fp32 reference semantics) ----------------
__global__ void rope_table_kernel() {
    int idx = blockIdx.x * blockDim.x + threadIdx.x;
    if (idx >= TT * 64) return;
    int t = idx >> 6, i = idx & 63;
    float invf = (float)(1.0 / pow(10000.0, (double)i / 64.0));
    float ang = (float)t * invf;
    double a = (double)ang;
    g_cos[idx] = (float)cos(a);
    g_sin[idx] = (float)sin(a);
}

// ---------------- in-place RoPE on Q and K slices of g_qkv ----------------
__global__ void rope_apply_kernel() {
    int idx = blockIdx.x * blockDim.x + threadIdx.x;
    int i = idx & 63; int r = idx >> 6;
    int h = r & (HH - 1); r >>= 4;
    int w = r & 1; r >>= 1;
    int t = r & (TT - 1); r >>= 11;
    int b = r;
    size_t base = ((size_t)(b * TT + t)) * C3 + (size_t)w * CC + (size_t)h * DD;
    float c = g_cos[t * 64 + i], s = g_sin[t * 64 + i];
    float x1 = g_qkv[base + i], x2 = g_qkv[base + 64 + i];
    g_qkv[base + i]      = x1 * c - x2 * s;
    g_qkv[base + 64 + i] = x2 * c + x1 * s;
}

// ---------------- common MMA helpers ----------------
__device__ __forceinline__ unsigned smem_u32(const void* p) {
    return (unsigned)__cvta_generic_to_shared(p);
}
__device__ __forceinline__ void split_tf32(float x, unsigned &hi, unsigned &lo) {
    unsigned h;
    asm("cvt.rna.tf32.f32 %0, %1;" : "=r"(h) : "f"(x));
    float l = x - __uint_as_float(h);
    unsigned lw;
    asm("cvt.rna.tf32.f32 %0, %1;" : "=r"(lw) : "f"(l));
    hi = h; lo = lw;
}
__device__ __forceinline__ float to_tf32(float x) {
    unsigned u;
    asm("cvt.rna.tf32.f32 %0, %1;" : "=r"(u) : "f"(x));
    return __uint_as_float(u);
}
__device__ __forceinline__ void mma_tf32(float* d, const unsigned* a, const unsigned* b) {
    asm volatile(
        "mma.sync.aligned.m16n8k8.row.col.f32.tf32.tf32.f32 "
        "{%0,%1,%2,%3}, {%4,%5,%6,%7}, {%8,%9}, {%0,%1,%2,%3};"
        : "+f"(d[0]), "+f"(d[1]), "+f"(d[2]), "+f"(d[3])
        : "r"(a[0]), "r"(a[1]), "r"(a[2]), "r"(a[3]), "r"(b[0]), "r"(b[1]));
}

// ================= 3xTF32 tensor-core GEMM: C[M,N] = A[M,K] @ B[K,N] ==============
#define KC 32
#define AGS 36
#define BGS 136
#define ABUF (128 * AGS)
#define BBUF (KC * BGS)
#define GEMM_SMEM ((2 * ABUF + 2 * BBUF) * 4)

__device__ __forceinline__ void gemm_load_chunk(
    float* As, float* Bs, const float* __restrict__ A, const float* __restrict__ B,
    int row0, int col0, int kc, int K, int N, int tid)
{
#pragma unroll
    for (int i = 0; i < 8; i++) {
        int idx = i * 128 + tid;
        int row = idx >> 3, seg = (idx & 7) << 2;
        unsigned dst = smem_u32(As + row * AGS + seg);
        const float* src = A + (size_t)(row0 + row) * K + kc + seg;
        asm volatile("cp.async.cg.shared.global [%0], [%1], 16;" :: "r"(dst), "l"(src));
    }
#pragma unroll
    for (int i = 0; i < 8; i++) {
        int idx = i * 128 + tid;
        int row = idx >> 5, seg = (idx & 31) << 2;
        unsigned dst = smem_u32(Bs + row * BGS + seg);
        const float* src = B + (size_t)(kc + row) * N + col0 + seg;
        asm volatile("cp.async.cg.shared.global [%0], [%1], 16;" :: "r"(dst), "l"(src));
    }
    asm volatile("cp.async.commit_group;");
}

__global__ __launch_bounds__(128, 2) void gemm_tf32_kernel(
    const float* __restrict__ A, const float* __restrict__ B, float* __restrict__ C,
    int M, int N, int K)
{
    extern __shared__ float sm[];
    float* As = sm;
    float* Bs = sm + 2 * ABUF;
    const int tid  = threadIdx.x;
    const int lane = tid & 31, warp = tid >> 5;
    const int wr = warp >> 1, wc = warp & 1;
    const int gr = lane >> 2, tig = lane & 3;
    const int row0 = blockIdx.y * 128, col0 = blockIdx.x * 128;

    float acc[4][8][4];
#pragma unroll
    for (int mi = 0; mi < 4; mi++)
#pragma unroll
        for (int ni = 0; ni < 8; ni++)
#pragma unroll
            for (int r = 0; r < 4; r++) acc[mi][ni][r] = 0.f;

    const int nc = K / KC;
    gemm_load_chunk(As, Bs, A, B, row0, col0, 0, K, N, tid);

    for (int c = 0; c < nc; c++) {
        if (c + 1 < nc) {
            gemm_load_chunk(As + ((c + 1) & 1) * ABUF, Bs + ((c + 1) & 1) * BBUF,
                            A, B, row0, col0, (c + 1) * KC, K, N, tid);
            asm volatile("cp.async.wait_group 1;");
        } else {
            asm volatile("cp.async.wait_group 0;");
        }
        __syncthreads();

        const float* a = As + (c & 1) * ABUF;
        const float* b = Bs + (c & 1) * BBUF;
#pragma unroll
        for (int ks = 0; ks < 4; ks++) {
            const int k0 = ks * 8;
            unsigned afh[4][4], afl[4][4], bfh[8][2], bfl[8][2];
#pragma unroll
            for (int mi = 0; mi < 4; mi++) {
                int m0 = wr * 64 + mi * 16;
                split_tf32(a[(m0 + gr)     * AGS + k0 + tig],     afh[mi][0], afl[mi][0]);
                split_tf32(a[(m0 + 8 + gr) * AGS + k0 + tig],     afh[mi][1], afl[mi][1]);
                split_tf32(a[(m0 + gr)     * AGS + k0 + 4 + tig], afh[mi][2], afl[mi][2]);
                split_tf32(a[(m0 + 8 + gr) * AGS + k0 + 4 + tig], afh[mi][3], afl[mi][3]);
            }
#pragma unroll
            for (int ni = 0; ni < 8; ni++) {
                int n0 = wc * 64 + ni * 8;
                split_tf32(b[(k0 + tig)     * BGS + n0 + gr], bfh[ni][0], bfl[ni][0]);
                split_tf32(b[(k0 + 4 + tig) * BGS + n0 + gr], bfh[ni][1], bfl[ni][1]);
            }
#pragma unroll
            for (int mi = 0; mi < 4; mi++)
#pragma unroll
                for (int ni = 0; ni < 8; ni++) {
                    mma_tf32(acc[mi][ni], afl[mi], bfh[ni]);
                    mma_tf32(acc[mi][ni], afh[mi], bfl[ni]);
                    mma_tf32(acc[mi][ni], afh[mi], bfh[ni]);
                }
        }
        __syncthreads();
    }

#pragma unroll
    for (int mi = 0; mi < 4; mi++) {
        int m0 = row0 + wr * 64 + mi * 16;
#pragma unroll
        for (int ni = 0; ni < 8; ni++) {
            int n0 = col0 + wc * 64 + ni * 8 + 2 * tig;
            float* p0 = C + (size_t)(m0 + gr) * N + n0;
            float* p1 = C + (size_t)(m0 + 8 + gr) * N + n0;
            p0[0] = acc[mi][ni][0]; p0[1] = acc[mi][ni][1];
            p1[0] = acc[mi][ni][2]; p1[1] = acc[mi][ni][3];
        }
    }
}

// ========== tf32 tensor-core flash attention, causal, 64x64 tiles, D=128 ==========
// 256 threads / 8 warps. warp = (wr, wn): wr*16 rows; wn = n-half.
// Q/K/V/P rounded to tf32 once at smem store; MMA inner loops are pure LDS+MMA.
#define QSTR 132    // bank = 4*gr + tig  (bijective)
#define VSTR 136    // bank = 8*tig + gr  (bijective)
#define SSTR 68     // bank = 4*gr + tig  (bijective)
#define SM_Q 0
#define SM_K (SM_Q + 64 * QSTR)
#define SM_V (SM_K + 64 * QSTR)
#define SM_S (SM_V + 64 * VSTR)
#define SM_ST (SM_S + 64 * SSTR)
#define ATT_SMEM_BYTES ((SM_ST + 192) * 4)

__global__ __launch_bounds__(256, 1) void attn_kernel() {
    extern __shared__ float sm[];
    float* Qs = sm + SM_Q;
    float* Ks = sm + SM_K;
    float* Vs = sm + SM_V;
    float* Ss = sm + SM_S;
    float* mrow = sm + SM_ST;
    float* lrow = mrow + 64;
    float* crow = lrow + 64;

    const int tid = threadIdx.x;
    const int lane = tid & 31, warp = tid >> 5;
    const int gr = lane >> 2, tig = lane & 3;
    const int wr = warp >> 1, wn = warp & 1;
    const int m0 = wr * 16;
    const int bh = blockIdx.y;
    const int b = bh >> 4, h = bh & 15;
    const int qi = (int)gridDim.x - 1 - (int)blockIdx.x;  // heavy tiles first
    const int qbase = qi * 64;

    const float* Qg = g_qkv + (size_t)b * TT * C3 + (size_t)h * DD;
    const float* Kg = Qg + CC;
    const float* Vg = Qg + 2 * CC;

    // load Q tile (tf32-rounded)
#pragma unroll
    for (int l = 0; l < 8; l++) {
        int lin = l * 256 + tid;
        int row = lin >> 5, c4 = (lin & 31) << 2;
        float4 v = *(const float4*)&Qg[(size_t)(qbase + row) * C3 + c4];
        v.x = to_tf32(v.x); v.y = to_tf32(v.y); v.z = to_tf32(v.z); v.w = to_tf32(v.w);
        *(float4*)&Qs[row * QSTR + c4] = v;
    }
    if (tid < 64) { mrow[tid] = -INFINITY; lrow[tid] = 0.f; }

    float oacc[8][4];
#pragma unroll
    for (int ni = 0; ni < 8; ni++)
#pragma unroll
        for (int r = 0; r < 4; r++) oacc[ni][r] = 0.f;
    __syncthreads();

    const float scale = 0.08838834764831845f;  // 1/sqrt(128)

    for (int kt = 0; kt <= qi; kt++) {
        // load K,V tiles (tf32-rounded)
#pragma unroll
        for (int l = 0; l < 8; l++) {
            int lin = l * 256 + tid;
            int row = lin >> 5, c4 = (lin & 31) << 2;
            size_t gofs = (size_t)(kt * 64 + row) * C3 + c4;
            float4 kv = *(const float4*)&Kg[gofs];
            kv.x = to_tf32(kv.x); kv.y = to_tf32(kv.y); kv.z = to_tf32(kv.z); kv.w = to_tf32(kv.w);
            *(float4*)&Ks[row * QSTR + c4] = kv;
            float4 vv = *(const float4*)&Vg[gofs];
            vv.x = to_tf32(vv.x); vv.y = to_tf32(vv.y); vv.z = to_tf32(vv.z); vv.w = to_tf32(vv.w);
            *(float4*)&Vs[row * VSTR + c4] = vv;
        }
        __syncthreads();

        // S = Q @ K^T via MMA: warp tile m16 x n32
        float sa[4][4];
#pragma unroll
        for (int ni = 0; ni < 4; ni++)
#pragma unroll
            for (int r = 0; r < 4; r++) sa[ni][r] = 0.f;

#pragma unroll
        for (int ks = 0; ks < 16; ks++) {
            const int k0 = ks * 8;
            unsigned a[4];
            a[0] = __float_as_uint(Qs[(m0 + gr)     * QSTR + k0 + tig]);
            a[1] = __float_as_uint(Qs[(m0 + 8 + gr) * QSTR + k0 + tig]);
            a[2] = __float_as_uint(Qs[(m0 + gr)     * QSTR + k0 + 4 + tig]);
            a[3] = __float_as_uint(Qs[(m0 + 8 + gr) * QSTR + k0 + 4 + tig]);
#pragma unroll
            for (int ni = 0; ni < 4; ni++) {
                int n0 = wn * 32 + ni * 8;
                unsigned bfr[2];
                bfr[0] = __float_as_uint(Ks[(n0 + gr) * QSTR + k0 + tig]);
                bfr[1] = __float_as_uint(Ks[(n0 + gr) * QSTR + k0 + 4 + tig]);
                mma_tf32(sa[ni], a, bfr);
            }
        }

        // write scaled + masked S to smem
        const bool diag = (kt == qi);
#pragma unroll
        for (int ni = 0; ni < 4; ni++) {
            int c0 = wn * 32 + ni * 8 + 2 * tig;
            int r0 = m0 + gr, r1 = m0 + 8 + gr;
            float v0 = sa[ni][0] * scale, v1 = sa[ni][1] * scale;
            float v2 = sa[ni][2] * scale, v3 = sa[ni][3] * scale;
            if (diag) {
                if (c0     > r0) v0 = -INFINITY;
                if (c0 + 1 > r0) v1 = -INFINITY;
                if (c0     > r1) v2 = -INFINITY;
                if (c0 + 1 > r1) v3 = -INFINITY;
            }
            Ss[r0 * SSTR + c0] = v0; Ss[r0 * SSTR + c0 + 1] = v1;
            Ss[r1 * SSTR + c0] = v2; Ss[r1 * SSTR + c0 + 1] = v3;
        }
        __syncthreads();

        // online softmax (row-wise, 4 lanes per row); store P tf32-rounded
        {
            int r = tid >> 2, sub = tid & 3;
            int cbase = sub * 16;
            float mx = -INFINITY;
#pragma unroll
            for (int c = 0; c < 16; c++) mx = fmaxf(mx, Ss[r * SSTR + cbase + c]);
            mx = fmaxf(mx, __shfl_xor_sync(0xffffffffu, mx, 1));
            mx = fmaxf(mx, __shfl_xor_sync(0xffffffffu, mx, 2));
            float mold = mrow[r];
            float mnew = fmaxf(mold, mx);
            float s = 0.f;
#pragma unroll
            for (int c = 0; c < 16; c++) {
                float p = expf(Ss[r * SSTR + cbase + c] - mnew);
                Ss[r * SSTR + cbase + c] = to_tf32(p);
                s += p;
            }
            s += __shfl_xor_sync(0xffffffffu, s, 1);
            s += __shfl_xor_sync(0xffffffffu, s, 2);
            if (sub == 0) {
                float cf = expf(mold - mnew);
                lrow[r] = lrow[r] * cf + s;
                mrow[r] = mnew;
                crow[r] = cf;
            }
        }
        __syncthreads();

        // O = O*cf + P @ V via MMA: warp tile m16 x n64
        {
            float cf0 = crow[m0 + gr], cf1 = crow[m0 + 8 + gr];
#pragma unroll
            for (int ni = 0; ni < 8; ni++) {
                oacc[ni][0] *= cf0; oacc[ni][1] *= cf0;
                oacc[ni][2] *= cf1; oacc[ni][3] *= cf1;
            }
        }
#pragma unroll
        for (int ks = 0; ks < 8; ks++) {
            const int k0 = ks * 8;
            unsigned a[4];
            a[0] = __float_as_uint(Ss[(m0 + gr)     * SSTR + k0 + tig]);
            a[1] = __float_as_uint(Ss[(m0 + 8 + gr) * SSTR + k0 + tig]);
            a[2] = __float_as_uint(Ss[(m0 + gr)     * SSTR + k0 + 4 + tig]);
            a[3] = __float_as_uint(Ss[(m0 + 8 + gr) * SSTR + k0 + 4 + tig]);
#pragma unroll
            for (int ni = 0; ni < 8; ni++) {
                int n0 = wn * 64 + ni * 8;
                unsigned bfr[2];
                bfr[0] = __float_as_uint(Vs[(k0 + tig)     * VSTR + n0 + gr]);
                bfr[1] = __float_as_uint(Vs[(k0 + 4 + tig) * VSTR + n0 + gr]);
                mma_tf32(oacc[ni], a, bfr);
            }
        }
        __syncthreads();
    }

    // epilogue: normalize, zero padded rows, write [B,T,C]
    {
        int len = g_len[b];
        int r0 = m0 + gr, r1 = m0 + 8 + gr;
        int t0 = qbase + r0, t1 = qbase + r1;
        float inv0 = (t0 < len) ? 1.0f / lrow[r0] : 0.f;
        float inv1 = (t1 < len) ? 1.0f / lrow[r1] : 0.f;
        float* d0 = g_attn + ((size_t)b * TT + t0) * CC + (size_t)h * DD;
        float* d1 = g_attn + ((size_t)b * TT + t1) * CC + (size_t)h * DD;
#pragma unroll
        for (int ni = 0; ni < 8; ni++) {
            int c = wn * 64 + ni * 8 + 2 * tig;
            d0[c] = oacc[ni][0] * inv0; d0[c + 1] = oacc[ni][1] * inv0;
            d1[c] = oacc[ni][2] * inv1; d1[c + 1] = oacc[ni][3] * inv1;
        }
    }
}

// ---------------- launch ----------------
extern "C" void kernel_launch(void* const* d_in, const int* in_sizes, int n_in,
                              void* d_out, int out_size) {
    const float* x    = (const float*)d_in[0];
    const void*  mask = d_in[1];
    const float* Wqkv = (const float*)d_in[2];
    const float* Wout = (const float*)d_in[3];
    float* out = (float*)d_out;

    float* qkv;  cudaGetSymbolAddress((void**)&qkv,  g_qkv);
    float* attn; cudaGetSymbolAddress((void**)&attn, g_attn);

    lengths_kernel<<<BB, 256>>>(mask);
    rope_table_kernel<<<(TT * 64 + 255) / 256, 256>>>();

    cudaFuncSetAttribute(gemm_tf32_kernel, cudaFuncAttributeMaxDynamicSharedMemorySize, GEMM_SMEM);

    // qkv = x @ Wqkv  : [4096,2048] @ [2048,6144]  (3xTF32 tensor cores)
    gemm_tf32_kernel<<<dim3(C3 / 128, BT / 128), 128, GEMM_SMEM>>>(x, Wqkv, qkv, BT, C3, CC);

    // RoPE in place on Q,K
    rope_apply_kernel<<<(BB * TT * 2 * HH * 64) / 256, 256>>>();

    // causal flash attention (tf32 tensor cores)
    cudaFuncSetAttribute(attn_kernel, cudaFuncAttributeMaxDynamicSharedMemorySize, ATT_SMEM_BYTES);
    attn_kernel<<<dim3(TT / 64, BB * HH), 256, ATT_SMEM_BYTES>>>();

    // out = attn @ Wout : [4096,2048] @ [2048,2048]  (3xTF32 tensor cores)
    gemm_tf32_kernel<<<dim3(CC / 128, BT / 128), 128, GEMM_SMEM>>>(attn, Wout, out, BT, CC, CC);
}

// round 6
// speedup vs baseline: 2.7368x; 1.6541x over previous
#include <cuda_runtime.h>
#include <cuda_bf16.h>
#include <math.h>

#define BB 2
#define TT 2048
#define CC 2048
#define HH 16
#define DD 128
#define C3 (3*CC)
#define BT (BB*TT)

// ---------------- device scratch (static: no allocations allowed) ----------------
__device__ float g_qkv[(size_t)BT * C3];            // [B,T,3C] fp32
__device__ unsigned g_xh[(size_t)BT * CC / 2];      // x hi  (bf16 pairs, [BT][CC/2] words)
__device__ unsigned g_xl[(size_t)BT * CC / 2];      // x lo
__device__ unsigned g_ah[(size_t)BT * CC / 2];      // attn out hi
__device__ unsigned g_al[(size_t)BT * CC / 2];      // attn out lo
__device__ unsigned g_wqkvh[(size_t)(CC/2) * C3];   // Wqkv hi, k-pair packed [K/2][N]
__device__ unsigned g_wqkvl[(size_t)(CC/2) * C3];
__device__ unsigned g_wouth[(size_t)(CC/2) * CC];
__device__ unsigned g_woutl[(size_t)(CC/2) * CC];
__device__ float g_cos[TT * 64];
__device__ float g_sin[TT * 64];
__device__ int   g_len[BB];

// ---------------- lengths from padding mask (dtype auto-detect) ----------------
__global__ void lengths_kernel(const void* mask) {
    __shared__ int ssum[256];
    int b = blockIdx.x;
    unsigned int w0 = *(const unsigned int*)mask;
    int cnt = 0;
    if (w0 == 0x01010101u) {
        const unsigned char* m = (const unsigned char*)mask + (size_t)b * TT;
        for (int i = threadIdx.x; i < TT; i += 256) cnt += (m[i] != 0);
    } else if (w0 == 0x3F800000u) {
        const float* m = (const float*)mask + (size_t)b * TT;
        for (int i = threadIdx.x; i < TT; i += 256) cnt += (m[i] != 0.0f);
    } else {
        const int* m = (const int*)mask + (size_t)b * TT;
        for (int i = threadIdx.x; i < TT; i += 256) cnt += (m[i] != 0);
    }
    ssum[threadIdx.x] = cnt;
    __syncthreads();
    for (int s = 128; s > 0; s >>= 1) {
        if (threadIdx.x < s) ssum[threadIdx.x] += ssum[threadIdx.x + s];
        __syncthreads();
    }
    if (threadIdx.x == 0) g_len[b] = ssum[0];
}

// ---------------- RoPE tables ----------------
__global__ void rope_table_kernel() {
    int idx = blockIdx.x * blockDim.x + threadIdx.x;
    if (idx >= TT * 64) return;
    int t = idx >> 6, i = idx & 63;
    float invf = (float)(1.0 / pow(10000.0, (double)i / 64.0));
    float ang = (float)t * invf;
    double a = (double)ang;
    g_cos[idx] = (float)cos(a);
    g_sin[idx] = (float)sin(a);
}

// ---------------- in-place RoPE on Q and K slices of g_qkv ----------------
__global__ void rope_apply_kernel() {
    int idx = blockIdx.x * blockDim.x + threadIdx.x;
    int i = idx & 63; int r = idx >> 6;
    int h = r & (HH - 1); r >>= 4;
    int w = r & 1; r >>= 1;
    int t = r & (TT - 1); r >>= 11;
    int b = r;
    size_t base = ((size_t)(b * TT + t)) * C3 + (size_t)w * CC + (size_t)h * DD;
    float c = g_cos[t * 64 + i], s = g_sin[t * 64 + i];
    float x1 = g_qkv[base + i], x2 = g_qkv[base + 64 + i];
    g_qkv[base + i]      = x1 * c - x2 * s;
    g_qkv[base + 64 + i] = x2 * c + x1 * s;
}

// ---------------- helpers ----------------
__device__ __forceinline__ unsigned smem_u32(const void* p) {
    return (unsigned)__cvta_generic_to_shared(p);
}
__device__ __forceinline__ float to_tf32(float x) {
    unsigned u;
    asm("cvt.rna.tf32.f32 %0, %1;" : "=r"(u) : "f"(x));
    return __uint_as_float(u);
}
__device__ __forceinline__ void mma_tf32(float* d, const unsigned* a, const unsigned* b) {
    asm volatile(
        "mma.sync.aligned.m16n8k8.row.col.f32.tf32.tf32.f32 "
        "{%0,%1,%2,%3}, {%4,%5,%6,%7}, {%8,%9}, {%0,%1,%2,%3};"
        : "+f"(d[0]), "+f"(d[1]), "+f"(d[2]), "+f"(d[3])
        : "r"(a[0]), "r"(a[1]), "r"(a[2]), "r"(a[3]), "r"(b[0]), "r"(b[1]));
}
__device__ __forceinline__ void mma_bf16(float* d, const unsigned* a, const unsigned* b) {
    asm volatile(
        "mma.sync.aligned.m16n8k16.row.col.f32.bf16.bf16.f32 "
        "{%0,%1,%2,%3}, {%4,%5,%6,%7}, {%8,%9}, {%0,%1,%2,%3};"
        : "+f"(d[0]), "+f"(d[1]), "+f"(d[2]), "+f"(d[3])
        : "r"(a[0]), "r"(a[1]), "r"(a[2]), "r"(a[3]), "r"(b[0]), "r"(b[1]));
}
__device__ __forceinline__ unsigned pack_hi(float v0, float v1, float &r0, float &r1) {
    __nv_bfloat16 h0 = __float2bfloat16(v0);
    __nv_bfloat16 h1 = __float2bfloat16(v1);
    r0 = v0 - __bfloat162float(h0);
    r1 = v1 - __bfloat162float(h1);
    unsigned u0 = __bfloat16_as_ushort(h0), u1 = __bfloat16_as_ushort(h1);
    return u0 | (u1 << 16);
}
__device__ __forceinline__ unsigned pack_bf(float v0, float v1) {
    unsigned u0 = __bfloat16_as_ushort(__float2bfloat16(v0));
    unsigned u1 = __bfloat16_as_ushort(__float2bfloat16(v1));
    return u0 | (u1 << 16);
}

// ---------------- split kernels ----------------
// A-style: fp32 [M][K] row-major -> hi/lo word arrays [M][K/2]
__global__ void split_a_kernel(const float* __restrict__ src, unsigned* __restrict__ dh,
                               unsigned* __restrict__ dl, size_t nwords) {
    size_t w = (size_t)blockIdx.x * blockDim.x + threadIdx.x;
    if (w >= nwords) return;
    float2 v = *(const float2*)&src[w * 2];
    float l0, l1;
    dh[w] = pack_hi(v.x, v.y, l0, l1);
    dl[w] = pack_bf(l0, l1);
}

// B-style: fp32 [K][N] -> k-pair packed hi/lo words [K/2][N]
__global__ void split_b_kernel(const float* __restrict__ W, unsigned* __restrict__ dh,
                               unsigned* __restrict__ dl, int K, int N) {
    size_t idx = (size_t)blockIdx.x * blockDim.x + threadIdx.x;
    size_t tot = (size_t)(K / 2) * N;
    if (idx >= tot) return;
    int n = (int)(idx % N);
    int k2 = (int)(idx / N);
    float v0 = W[(size_t)(2 * k2) * N + n];
    float v1 = W[(size_t)(2 * k2 + 1) * N + n];
    float l0, l1;
    dh[idx] = pack_hi(v0, v1, l0, l1);
    dl[idx] = pack_bf(l0, l1);
}

// ================= bf16x3 tensor-core GEMM: C[M,N] = A[M,K] @ B[K,N] ==============
// A: hi/lo word arrays [M][K/2]; B: k-pair packed hi/lo [K/2][N].
// CTA 128x128, 4 warps 2x2 (warp tile 64x64), KC=32 double-buffered cp.async.
#define KCB 32
#define ASTRW 20                 // A smem row stride in words (40 bf16): bank=(20*gr+tig)%32 bijective
#define BSTRW 136                // B smem row stride in words: bank=(8*tig+gr)%32 bijective
#define ATILEW (128 * ASTRW)     // 2560 words
#define BTILEW (16 * BSTRW)      // 2176 words
#define GEMM_SMEM ((4 * ATILEW + 4 * BTILEW) * 4)   // hi+lo, double buffered = 75776 B

__device__ __forceinline__ void gemm_load_chunk_bf(
    unsigned* Ah, unsigned* Al, unsigned* Bh, unsigned* Bl,
    const unsigned* __restrict__ Agh, const unsigned* __restrict__ Agl,
    const unsigned* __restrict__ Bgh, const unsigned* __restrict__ Bgl,
    int row0, int col0, int kc, int K, int N, int tid)
{
    const int Kw = K >> 1;
#pragma unroll
    for (int i = 0; i < 4; i++) {                 // A: 128 rows x 16 words, 4 chunks/row-group
        int c = i * 128 + tid;
        int row = c >> 2, segw = (c & 3) << 2;
        size_t gsrc = (size_t)(row0 + row) * Kw + (kc >> 1) + segw;
        int dstw = row * ASTRW + segw;
        asm volatile("cp.async.cg.shared.global [%0], [%1], 16;"
                     :: "r"(smem_u32(Ah + dstw)), "l"(Agh + gsrc));
        asm volatile("cp.async.cg.shared.global [%0], [%1], 16;"
                     :: "r"(smem_u32(Al + dstw)), "l"(Agl + gsrc));
    }
#pragma unroll
    for (int i = 0; i < 4; i++) {                 // B: 16 k'-rows x 128 words
        int c = i * 128 + tid;
        int krow = c >> 5, segw = (c & 31) << 2;
        size_t gsrc = (size_t)((kc >> 1) + krow) * N + col0 + segw;
        int dstw = krow * BSTRW + segw;
        asm volatile("cp.async.cg.shared.global [%0], [%1], 16;"
                     :: "r"(smem_u32(Bh + dstw)), "l"(Bgh + gsrc));
        asm volatile("cp.async.cg.shared.global [%0], [%1], 16;"
                     :: "r"(smem_u32(Bl + dstw)), "l"(Bgl + gsrc));
    }
    asm volatile("cp.async.commit_group;");
}

__global__ __launch_bounds__(128, 2) void gemm_bf16x3_kernel(
    const unsigned* __restrict__ Agh, const unsigned* __restrict__ Agl,
    const unsigned* __restrict__ Bgh, const unsigned* __restrict__ Bgl,
    float* __restrict__ C, int M, int N, int K)
{
    extern __shared__ unsigned smw[];
    unsigned* Ah = smw;                    // [2][ATILEW]
    unsigned* Al = smw + 2 * ATILEW;
    unsigned* Bh = smw + 4 * ATILEW;       // [2][BTILEW]
    unsigned* Bl = smw + 4 * ATILEW + 2 * BTILEW;

    const int tid  = threadIdx.x;
    const int lane = tid & 31, warp = tid >> 5;
    const int wr = warp >> 1, wc = warp & 1;
    const int gr = lane >> 2, tig = lane & 3;
    const int row0 = blockIdx.y * 128, col0 = blockIdx.x * 128;

    float acc[4][8][4];
#pragma unroll
    for (int mi = 0; mi < 4; mi++)
#pragma unroll
        for (int ni = 0; ni < 8; ni++)
#pragma unroll
            for (int r = 0; r < 4; r++) acc[mi][ni][r] = 0.f;

    const int nc = K / KCB;
    gemm_load_chunk_bf(Ah, Al, Bh, Bl, Agh, Agl, Bgh, Bgl, row0, col0, 0, K, N, tid);

    for (int c = 0; c < nc; c++) {
        if (c + 1 < nc) {
            int nb = (c + 1) & 1;
            gemm_load_chunk_bf(Ah + nb * ATILEW, Al + nb * ATILEW,
                               Bh + nb * BTILEW, Bl + nb * BTILEW,
                               Agh, Agl, Bgh, Bgl, row0, col0, (c + 1) * KCB, K, N, tid);
            asm volatile("cp.async.wait_group 1;");
        } else {
            asm volatile("cp.async.wait_group 0;");
        }
        __syncthreads();

        const unsigned* ah = Ah + (c & 1) * ATILEW;
        const unsigned* al = Al + (c & 1) * ATILEW;
        const unsigned* bh = Bh + (c & 1) * BTILEW;
        const unsigned* bl = Bl + (c & 1) * BTILEW;

#pragma unroll
        for (int s = 0; s < 2; s++) {             // two k16 steps per chunk
            const int kw = s * 8;
            unsigned afh[4][4], afl[4][4], bfh[8][2], bfl[8][2];
#pragma unroll
            for (int mi = 0; mi < 4; mi++) {
                int m0 = wr * 64 + mi * 16;
                int w0 = (m0 + gr) * ASTRW + kw + tig;
                int w1 = (m0 + 8 + gr) * ASTRW + kw + tig;
                afh[mi][0] = ah[w0];     afh[mi][1] = ah[w1];
                afh[mi][2] = ah[w0 + 4]; afh[mi][3] = ah[w1 + 4];
                afl[mi][0] = al[w0];     afl[mi][1] = al[w1];
                afl[mi][2] = al[w0 + 4]; afl[mi][3] = al[w1 + 4];
            }
#pragma unroll
            for (int ni = 0; ni < 8; ni++) {
                int n0 = wc * 64 + ni * 8;
                int w0 = (kw + tig) * BSTRW + n0 + gr;
                int w1 = (kw + 4 + tig) * BSTRW + n0 + gr;
                bfh[ni][0] = bh[w0]; bfh[ni][1] = bh[w1];
                bfl[ni][0] = bl[w0]; bfl[ni][1] = bl[w1];
            }
#pragma unroll
            for (int mi = 0; mi < 4; mi++)
#pragma unroll
                for (int ni = 0; ni < 8; ni++) {
                    mma_bf16(acc[mi][ni], afl[mi], bfh[ni]);   // lo*hi
                    mma_bf16(acc[mi][ni], afh[mi], bfl[ni]);   // hi*lo
                    mma_bf16(acc[mi][ni], afh[mi], bfh[ni]);   // hi*hi
                }
        }
        __syncthreads();
    }

#pragma unroll
    for (int mi = 0; mi < 4; mi++) {
        int m0 = row0 + wr * 64 + mi * 16;
#pragma unroll
        for (int ni = 0; ni < 8; ni++) {
            int n0 = col0 + wc * 64 + ni * 8 + 2 * tig;
            float* p0 = C + (size_t)(m0 + gr) * N + n0;
            float* p1 = C + (size_t)(m0 + 8 + gr) * N + n0;
            p0[0] = acc[mi][ni][0]; p0[1] = acc[mi][ni][1];
            p1[0] = acc[mi][ni][2]; p1[1] = acc[mi][ni][3];
        }
    }
}

// ========== tf32 tensor-core flash attention, causal, 64x64 tiles, D=128 ==========
#define QSTR 132
#define VSTR 136
#define SSTR 68
#define SM_Q 0
#define SM_K (SM_Q + 64 * QSTR)
#define SM_V (SM_K + 64 * QSTR)
#define SM_S (SM_V + 64 * VSTR)
#define SM_ST (SM_S + 64 * SSTR)
#define ATT_SMEM_BYTES ((SM_ST + 192) * 4)

__global__ __launch_bounds__(256, 1) void attn_kernel() {
    extern __shared__ float sm[];
    float* Qs = sm + SM_Q;
    float* Ks = sm + SM_K;
    float* Vs = sm + SM_V;
    float* Ss = sm + SM_S;
    float* mrow = sm + SM_ST;
    float* lrow = mrow + 64;
    float* crow = lrow + 64;

    const int tid = threadIdx.x;
    const int lane = tid & 31, warp = tid >> 5;
    const int gr = lane >> 2, tig = lane & 3;
    const int wr = warp >> 1, wn = warp & 1;
    const int m0 = wr * 16;
    const int bh = blockIdx.y;
    const int b = bh >> 4, h = bh & 15;
    const int qi = (int)gridDim.x - 1 - (int)blockIdx.x;
    const int qbase = qi * 64;

    const float* Qg = g_qkv + (size_t)b * TT * C3 + (size_t)h * DD;
    const float* Kg = Qg + CC;
    const float* Vg = Qg + 2 * CC;

#pragma unroll
    for (int l = 0; l < 8; l++) {
        int lin = l * 256 + tid;
        int row = lin >> 5, c4 = (lin & 31) << 2;
        float4 v = *(const float4*)&Qg[(size_t)(qbase + row) * C3 + c4];
        v.x = to_tf32(v.x); v.y = to_tf32(v.y); v.z = to_tf32(v.z); v.w = to_tf32(v.w);
        *(float4*)&Qs[row * QSTR + c4] = v;
    }
    if (tid < 64) { mrow[tid] = -INFINITY; lrow[tid] = 0.f; }

    float oacc[8][4];
#pragma unroll
    for (int ni = 0; ni < 8; ni++)
#pragma unroll
        for (int r = 0; r < 4; r++) oacc[ni][r] = 0.f;
    __syncthreads();

    const float scale = 0.08838834764831845f;

    for (int kt = 0; kt <= qi; kt++) {
#pragma unroll
        for (int l = 0; l < 8; l++) {
            int lin = l * 256 + tid;
            int row = lin >> 5, c4 = (lin & 31) << 2;
            size_t gofs = (size_t)(kt * 64 + row) * C3 + c4;
            float4 kv = *(const float4*)&Kg[gofs];
            kv.x = to_tf32(kv.x); kv.y = to_tf32(kv.y); kv.z = to_tf32(kv.z); kv.w = to_tf32(kv.w);
            *(float4*)&Ks[row * QSTR + c4] = kv;
            float4 vv = *(const float4*)&Vg[gofs];
            vv.x = to_tf32(vv.x); vv.y = to_tf32(vv.y); vv.z = to_tf32(vv.z); vv.w = to_tf32(vv.w);
            *(float4*)&Vs[row * VSTR + c4] = vv;
        }
        __syncthreads();

        float sa[4][4];
#pragma unroll
        for (int ni = 0; ni < 4; ni++)
#pragma unroll
            for (int r = 0; r < 4; r++) sa[ni][r] = 0.f;

#pragma unroll
        for (int ks = 0; ks < 16; ks++) {
            const int k0 = ks * 8;
            unsigned a[4];
            a[0] = __float_as_uint(Qs[(m0 + gr)     * QSTR + k0 + tig]);
            a[1] = __float_as_uint(Qs[(m0 + 8 + gr) * QSTR + k0 + tig]);
            a[2] = __float_as_uint(Qs[(m0 + gr)     * QSTR + k0 + 4 + tig]);
            a[3] = __float_as_uint(Qs[(m0 + 8 + gr) * QSTR + k0 + 4 + tig]);
#pragma unroll
            for (int ni = 0; ni < 4; ni++) {
                int n0 = wn * 32 + ni * 8;
                unsigned bfr[2];
                bfr[0] = __float_as_uint(Ks[(n0 + gr) * QSTR + k0 + tig]);
                bfr[1] = __float_as_uint(Ks[(n0 + gr) * QSTR + k0 + 4 + tig]);
                mma_tf32(sa[ni], a, bfr);
            }
        }

        const bool diag = (kt == qi);
#pragma unroll
        for (int ni = 0; ni < 4; ni++) {
            int c0 = wn * 32 + ni * 8 + 2 * tig;
            int r0 = m0 + gr, r1 = m0 + 8 + gr;
            float v0 = sa[ni][0] * scale, v1 = sa[ni][1] * scale;
            float v2 = sa[ni][2] * scale, v3 = sa[ni][3] * scale;
            if (diag) {
                if (c0     > r0) v0 = -INFINITY;
                if (c0 + 1 > r0) v1 = -INFINITY;
                if (c0     > r1) v2 = -INFINITY;
                if (c0 + 1 > r1) v3 = -INFINITY;
            }
            Ss[r0 * SSTR + c0] = v0; Ss[r0 * SSTR + c0 + 1] = v1;
            Ss[r1 * SSTR + c0] = v2; Ss[r1 * SSTR + c0 + 1] = v3;
        }
        __syncthreads();

        {
            int r = tid >> 2, sub = tid & 3;
            int cbase = sub * 16;
            float mx = -INFINITY;
#pragma unroll
            for (int c = 0; c < 16; c++) mx = fmaxf(mx, Ss[r * SSTR + cbase + c]);
            mx = fmaxf(mx, __shfl_xor_sync(0xffffffffu, mx, 1));
            mx = fmaxf(mx, __shfl_xor_sync(0xffffffffu, mx, 2));
            float mold = mrow[r];
            float mnew = fmaxf(mold, mx);
            float s = 0.f;
#pragma unroll
            for (int c = 0; c < 16; c++) {
                float p = expf(Ss[r * SSTR + cbase + c] - mnew);
                Ss[r * SSTR + cbase + c] = to_tf32(p);
                s += p;
            }
            s += __shfl_xor_sync(0xffffffffu, s, 1);
            s += __shfl_xor_sync(0xffffffffu, s, 2);
            if (sub == 0) {
                float cf = expf(mold - mnew);
                lrow[r] = lrow[r] * cf + s;
                mrow[r] = mnew;
                crow[r] = cf;
            }
        }
        __syncthreads();

        {
            float cf0 = crow[m0 + gr], cf1 = crow[m0 + 8 + gr];
#pragma unroll
            for (int ni = 0; ni < 8; ni++) {
                oacc[ni][0] *= cf0; oacc[ni][1] *= cf0;
                oacc[ni][2] *= cf1; oacc[ni][3] *= cf1;
            }
        }
#pragma unroll
        for (int ks = 0; ks < 8; ks++) {
            const int k0 = ks * 8;
            unsigned a[4];
            a[0] = __float_as_uint(Ss[(m0 + gr)     * SSTR + k0 + tig]);
            a[1] = __float_as_uint(Ss[(m0 + 8 + gr) * SSTR + k0 + tig]);
            a[2] = __float_as_uint(Ss[(m0 + gr)     * SSTR + k0 + 4 + tig]);
            a[3] = __float_as_uint(Ss[(m0 + 8 + gr) * SSTR + k0 + 4 + tig]);
#pragma unroll
            for (int ni = 0; ni < 8; ni++) {
                int n0 = wn * 64 + ni * 8;
                unsigned bfr[2];
                bfr[0] = __float_as_uint(Vs[(k0 + tig)     * VSTR + n0 + gr]);
                bfr[1] = __float_as_uint(Vs[(k0 + 4 + tig) * VSTR + n0 + gr]);
                mma_tf32(oacc[ni], a, bfr);
            }
        }
        __syncthreads();
    }

    // epilogue: normalize, zero padded rows, write bf16 hi/lo (A operand of out-GEMM)
    {
        int len = g_len[b];
        int r0 = m0 + gr, r1 = m0 + 8 + gr;
        int t0 = qbase + r0, t1 = qbase + r1;
        float inv0 = (t0 < len) ? 1.0f / lrow[r0] : 0.f;
        float inv1 = (t1 < len) ? 1.0f / lrow[r1] : 0.f;
        size_t base0 = (((size_t)b * TT + t0) * CC + (size_t)h * DD) >> 1;
        size_t base1 = (((size_t)b * TT + t1) * CC + (size_t)h * DD) >> 1;
#pragma unroll
        for (int ni = 0; ni < 8; ni++) {
            int c = wn * 64 + ni * 8 + 2 * tig;
            float o0 = oacc[ni][0] * inv0, o1 = oacc[ni][1] * inv0;
            float o2 = oacc[ni][2] * inv1, o3 = oacc[ni][3] * inv1;
            float l0, l1, l2, l3;
            g_ah[base0 + (c >> 1)] = pack_hi(o0, o1, l0, l1);
            g_al[base0 + (c >> 1)] = pack_bf(l0, l1);
            g_ah[base1 + (c >> 1)] = pack_hi(o2, o3, l2, l3);
            g_al[base1 + (c >> 1)] = pack_bf(l2, l3);
        }
    }
}

// ---------------- launch ----------------
extern "C" void kernel_launch(void* const* d_in, const int* in_sizes, int n_in,
                              void* d_out, int out_size) {
    const float* x    = (const float*)d_in[0];
    const void*  mask = d_in[1];
    const float* Wqkv = (const float*)d_in[2];
    const float* Wout = (const float*)d_in[3];
    float* out = (float*)d_out;

    float* qkv;    cudaGetSymbolAddress((void**)&qkv,    g_qkv);
    unsigned *xh, *xl, *ah, *al, *wqh, *wql, *woh, *wol;
    cudaGetSymbolAddress((void**)&xh,  g_xh);
    cudaGetSymbolAddress((void**)&xl,  g_xl);
    cudaGetSymbolAddress((void**)&ah,  g_ah);
    cudaGetSymbolAddress((void**)&al,  g_al);
    cudaGetSymbolAddress((void**)&wqh, g_wqkvh);
    cudaGetSymbolAddress((void**)&wql, g_wqkvl);
    cudaGetSymbolAddress((void**)&woh, g_wouth);
    cudaGetSymbolAddress((void**)&wol, g_woutl);

    lengths_kernel<<<BB, 256>>>(mask);
    rope_table_kernel<<<(TT * 64 + 255) / 256, 256>>>();

    // pre-split operands to bf16 hi/lo
    {
        size_t nw = (size_t)BT * CC / 2;
        split_a_kernel<<<(unsigned)((nw + 255) / 256), 256>>>(x, xh, xl, nw);
        size_t nq = (size_t)(CC / 2) * C3;
        split_b_kernel<<<(unsigned)((nq + 255) / 256), 256>>>(Wqkv, wqh, wql, CC, C3);
        size_t no = (size_t)(CC / 2) * CC;
        split_b_kernel<<<(unsigned)((no + 255) / 256), 256>>>(Wout, woh, wol, CC, CC);
    }

    cudaFuncSetAttribute(gemm_bf16x3_kernel, cudaFuncAttributeMaxDynamicSharedMemorySize, GEMM_SMEM);

    // qkv = x @ Wqkv  (bf16x3 tensor cores)
    gemm_bf16x3_kernel<<<dim3(C3 / 128, BT / 128), 128, GEMM_SMEM>>>(
        xh, xl, wqh, wql, qkv, BT, C3, CC);

    // RoPE in place on Q,K
    rope_apply_kernel<<<(BB * TT * 2 * HH * 64) / 256, 256>>>();

    // causal flash attention (tf32 tensor cores), writes bf16 hi/lo attn output
    cudaFuncSetAttribute(attn_kernel, cudaFuncAttributeMaxDynamicSharedMemorySize, ATT_SMEM_BYTES);
    attn_kernel<<<dim3(TT / 64, BB * HH), 256, ATT_SMEM_BYTES>>>();

    // out = attn @ Wout  (bf16x3 tensor cores)
    gemm_bf16x3_kernel<<<dim3(CC / 128, BT / 128), 128, GEMM_SMEM>>>(
        ah, al, woh, wol, out, BT, CC, CC);
}